// round 2
// baseline (speedup 1.0000x reference)
#include <cuda_runtime.h>
#include <math.h>

// Problem constants
#define NL    3
#define BB    2
#define TT    1024
#define DD    1024
#define HH    16
#define NHKV  8
#define HDIM  64
#define MAXKV 3072
#define EPSF  1e-5f
#define MROWS (BB*TT)   // 2048

// ---------------- scratch (device globals; no cudaMalloc allowed) ----------------
__device__ float g_qtmp[MROWS * (NL*DD)];        // x @ q_w^T (all layers)   24 MB
__device__ float g_ktmp[MROWS * (NL*DD/2)];      // x @ k_w^T                12 MB
__device__ float g_vtmp[MROWS * (NL*DD/2)];      // x @ v_w^T                12 MB
__device__ float g_q [NL*BB*HH*TT*HDIM];         // rotated q [l][b][h][t][d] 24 MB
__device__ float g_Kc[BB*NHKV*MAXKV*HDIM];       // rotated K [b][kvh][pos][d] 12 MB
__device__ float g_Vc[BB*NHKV*MAXKV*HDIM];       // V          same layout    12 MB
__device__ float g_o [NL*MROWS*DD];              // attention out per layer   24 MB
__device__ float g_y [MROWS*DD];                 // pre-out-proj               8 MB

// ---------------- SGEMM: C[M][N] = A[M][K] * B[N][K]^T (row-major) ----------------
// 128x128 block tile, BK=8, 256 threads, 8x8 per thread. M,N%128==0, K%8==0.
__global__ __launch_bounds__(256) void sgemm_nt(const float* __restrict__ A,
                                                const float* __restrict__ B,
                                                float* __restrict__ C,
                                                int M, int N, int K) {
    __shared__ float As[8][128];
    __shared__ float Bs[8][128];
    const int tid = threadIdx.x;
    const int tx = tid & 15, ty = tid >> 4;
    const int lr = tid >> 1, lc = (tid & 1) * 4;
    const float* Ab = A + (size_t)(blockIdx.y * 128 + lr) * K + lc;
    const float* Bb = B + (size_t)(blockIdx.x * 128 + lr) * K + lc;
    float acc[8][8];
    #pragma unroll
    for (int i = 0; i < 8; i++)
        #pragma unroll
        for (int j = 0; j < 8; j++) acc[i][j] = 0.f;

    for (int k0 = 0; k0 < K; k0 += 8) {
        float4 a4 = *(const float4*)(Ab + k0);
        float4 b4 = *(const float4*)(Bb + k0);
        As[lc+0][lr] = a4.x; As[lc+1][lr] = a4.y; As[lc+2][lr] = a4.z; As[lc+3][lr] = a4.w;
        Bs[lc+0][lr] = b4.x; Bs[lc+1][lr] = b4.y; Bs[lc+2][lr] = b4.z; Bs[lc+3][lr] = b4.w;
        __syncthreads();
        #pragma unroll
        for (int k = 0; k < 8; k++) {
            float4 a0 = *(const float4*)&As[k][ty*8];
            float4 a1 = *(const float4*)&As[k][ty*8+4];
            float4 b0 = *(const float4*)&Bs[k][tx*8];
            float4 b1 = *(const float4*)&Bs[k][tx*8+4];
            float av[8] = {a0.x,a0.y,a0.z,a0.w,a1.x,a1.y,a1.z,a1.w};
            float bv[8] = {b0.x,b0.y,b0.z,b0.w,b1.x,b1.y,b1.z,b1.w};
            #pragma unroll
            for (int i = 0; i < 8; i++)
                #pragma unroll
                for (int j = 0; j < 8; j++)
                    acc[i][j] += av[i] * bv[j];
        }
        __syncthreads();
    }
    #pragma unroll
    for (int i = 0; i < 8; i++) {
        float* Cp = C + (size_t)(blockIdx.y*128 + ty*8 + i) * N + blockIdx.x*128 + tx*8;
        *(float4*)(Cp)     = make_float4(acc[i][0], acc[i][1], acc[i][2], acc[i][3]);
        *(float4*)(Cp + 4) = make_float4(acc[i][4], acc[i][5], acc[i][6], acc[i][7]);
    }
}

// ---------------- rope + scatter kernels ----------------
// q: qtmp[(b*T+t)][l*D + h*64 + d] -> rope(pos=t) -> g_q[l][b][h][t][d]
__global__ void rope_q_kernel(const float* __restrict__ qtmp,
                              const float* __restrict__ cosb,
                              const float* __restrict__ sinb,
                              float* __restrict__ gq) {
    int idx = blockIdx.x * blockDim.x + threadIdx.x;
    const int total = NL*BB*TT*HH*32;
    if (idx >= total) return;
    int d = idx & 31;  int r = idx >> 5;
    int h = r & 15;    r >>= 4;
    int t = r & 1023;  r >>= 10;
    int b = r & 1;     int l = r >> 1;
    const float* src = qtmp + (size_t)(b*TT + t)*(NL*DD) + l*DD + h*HDIM + d;
    float x1 = src[0], x2 = src[32];
    float c = cosb[t*32 + d], s = sinb[t*32 + d];
    float* dst = gq + ((size_t)((l*BB + b)*HH + h)*TT + t)*HDIM + d;
    dst[0]  = x1*c - x2*s;
    dst[32] = x2*c + x1*s;
}

// k: ktmp[(b*T+t)][l*512 + kvh*64 + d] -> rope(pos=l*T+t) -> g_Kc[b][kvh][l*T+t][d]
__global__ void rope_k_kernel(const float* __restrict__ ktmp,
                              const float* __restrict__ cosb,
                              const float* __restrict__ sinb,
                              float* __restrict__ gK) {
    int idx = blockIdx.x * blockDim.x + threadIdx.x;
    const int total = NL*BB*TT*NHKV*32;
    if (idx >= total) return;
    int d = idx & 31;  int r = idx >> 5;
    int kvh = r & 7;   r >>= 3;
    int t = r & 1023;  r >>= 10;
    int b = r & 1;     int l = r >> 1;
    const float* src = ktmp + (size_t)(b*TT + t)*(NL*DD/2) + l*(DD/2) + kvh*HDIM + d;
    float x1 = src[0], x2 = src[32];
    int pos = l*TT + t;
    float c = cosb[pos*32 + d], s = sinb[pos*32 + d];
    float* dst = gK + ((size_t)(b*NHKV + kvh)*MAXKV + pos)*HDIM + d;
    dst[0]  = x1*c - x2*s;
    dst[32] = x2*c + x1*s;
}

// v: plain scatter to g_Vc[b][kvh][l*T+t][d]
__global__ void copy_v_kernel(const float* __restrict__ vtmp, float* __restrict__ gV) {
    int idx = blockIdx.x * blockDim.x + threadIdx.x;
    const int total = NL*BB*TT*NHKV*HDIM;
    if (idx >= total) return;
    int d = idx & 63;  int r = idx >> 6;
    int kvh = r & 7;   r >>= 3;
    int t = r & 1023;  r >>= 10;
    int b = r & 1;     int l = r >> 1;
    gV[((size_t)(b*NHKV + kvh)*MAXKV + l*TT + t)*HDIM + d] =
        vtmp[(size_t)(b*TT + t)*(NL*DD/2) + l*(DD/2) + kvh*HDIM + d];
}

// ---------------- flash attention, fp32, 64x64 tiles ----------------
#define AP 68  // smem pitch (floats), keeps float4 alignment, kills bank conflicts
__global__ __launch_bounds__(256) void attn_kernel(const float* __restrict__ gq,
                                                   const float* __restrict__ gK,
                                                   const float* __restrict__ gV,
                                                   float* __restrict__ go) {
    extern __shared__ float sm[];
    float* Qs  = sm;             // [r][d]  64xAP
    float* Kst = sm + 64*AP;     // [d][c]  transposed K tile
    float* Vs  = sm + 2*64*AP;   // [c][d]
    float* Ps  = sm + 3*64*AP;   // [r][c]
    const int l  = blockIdx.z;
    const int bh = blockIdx.y;
    const int b = bh >> 4, h = bh & 15, kvh = h >> 1;
    const int q0 = blockIdx.x * 64;
    const int tid = threadIdx.x;
    const int tx = tid & 15, ty = tid >> 4;
    const int rr = tid >> 4, cc = (tid & 15) * 4;
    const float* Qb = gq + ((size_t)((l*BB + b)*HH + h)*TT + q0) * HDIM;
    const float* Kb = gK + (size_t)(b*NHKV + kvh) * MAXKV * HDIM;
    const float* Vb = gV + (size_t)(b*NHKV + kvh) * MAXKV * HDIM;

    #pragma unroll
    for (int it = 0; it < 4; it++) {
        int r = it*16 + rr;
        *(float4*)&Qs[r*AP + cc] = *(const float4*)(Qb + r*HDIM + cc);
    }

    float m[4], lsum[4], O[4][4];
    #pragma unroll
    for (int i = 0; i < 4; i++) {
        m[i] = -1e30f; lsum[i] = 0.f;
        #pragma unroll
        for (int j = 0; j < 4; j++) O[i][j] = 0.f;
    }

    const int nkt = l*16 + blockIdx.x + 1;   // key tiles; last one is the diagonal
    for (int kt = 0; kt < nkt; kt++) {
        const int p0 = kt * 64;
        __syncthreads();   // previous PV done with Vs/Ps; safe to overwrite tiles
        #pragma unroll
        for (int it = 0; it < 4; it++) {
            int c = it*16 + rr;
            float4 kv = *(const float4*)(Kb + (size_t)(p0 + c)*HDIM + cc);
            Kst[(cc+0)*AP + c] = kv.x;
            Kst[(cc+1)*AP + c] = kv.y;
            Kst[(cc+2)*AP + c] = kv.z;
            Kst[(cc+3)*AP + c] = kv.w;
            *(float4*)&Vs[c*AP + cc] = *(const float4*)(Vb + (size_t)(p0 + c)*HDIM + cc);
        }
        __syncthreads();

        float s[4][4];
        #pragma unroll
        for (int i = 0; i < 4; i++)
            #pragma unroll
            for (int j = 0; j < 4; j++) s[i][j] = 0.f;
        #pragma unroll 16
        for (int d = 0; d < 64; d++) {
            float a[4];
            #pragma unroll
            for (int i = 0; i < 4; i++) a[i] = Qs[(ty*4+i)*AP + d];
            float4 bv = *(const float4*)&Kst[d*AP + tx*4];
            #pragma unroll
            for (int i = 0; i < 4; i++) {
                s[i][0] += a[i]*bv.x; s[i][1] += a[i]*bv.y;
                s[i][2] += a[i]*bv.z; s[i][3] += a[i]*bv.w;
            }
        }
        const float scale = 0.125f;  // 64^-0.5
        if (kt == nkt - 1) {
            #pragma unroll
            for (int i = 0; i < 4; i++)
                #pragma unroll
                for (int j = 0; j < 4; j++)
                    s[i][j] = (tx*4+j <= ty*4+i) ? s[i][j]*scale : -1e30f;
        } else {
            #pragma unroll
            for (int i = 0; i < 4; i++)
                #pragma unroll
                for (int j = 0; j < 4; j++) s[i][j] *= scale;
        }
        #pragma unroll
        for (int i = 0; i < 4; i++) {
            float mx = fmaxf(fmaxf(s[i][0], s[i][1]), fmaxf(s[i][2], s[i][3]));
            #pragma unroll
            for (int off = 8; off > 0; off >>= 1)
                mx = fmaxf(mx, __shfl_xor_sync(0xffffffffu, mx, off));
            float mn = fmaxf(m[i], mx);
            float corr = __expf(m[i] - mn);
            m[i] = mn;
            float ps = 0.f;
            #pragma unroll
            for (int j = 0; j < 4; j++) { float p = __expf(s[i][j] - mn); s[i][j] = p; ps += p; }
            lsum[i] = lsum[i]*corr + ps;
            #pragma unroll
            for (int j = 0; j < 4; j++) O[i][j] *= corr;
            *(float4*)&Ps[(ty*4+i)*AP + tx*4] = make_float4(s[i][0], s[i][1], s[i][2], s[i][3]);
        }
        __syncthreads();
        #pragma unroll 16
        for (int c = 0; c < 64; c++) {
            float4 bv = *(const float4*)&Vs[c*AP + tx*4];
            float p[4];
            #pragma unroll
            for (int i = 0; i < 4; i++) p[i] = Ps[(ty*4+i)*AP + c];
            #pragma unroll
            for (int i = 0; i < 4; i++) {
                O[i][0] += p[i]*bv.x; O[i][1] += p[i]*bv.y;
                O[i][2] += p[i]*bv.z; O[i][3] += p[i]*bv.w;
            }
        }
    }
    #pragma unroll
    for (int i = 0; i < 4; i++) {
        float ls = lsum[i];
        #pragma unroll
        for (int off = 8; off > 0; off >>= 1)
            ls += __shfl_xor_sync(0xffffffffu, ls, off);
        float inv = 1.f / ls;
        int t = q0 + ty*4 + i;
        float* dst = go + ((size_t)(l*BB + b)*TT + t)*DD + h*HDIM + tx*4;
        *(float4*)dst = make_float4(O[i][0]*inv, O[i][1]*inv, O[i][2]*inv, O[i][3]*inv);
    }
}

// ---------------- combine: acc = sum_l lw_l * rmsnorm(o_l) ; y = rmsnorm(acc + a*x) ----------------
__device__ __forceinline__ float blockReduceSum256(float v, float* sbuf) {
    #pragma unroll
    for (int off = 16; off > 0; off >>= 1) v += __shfl_xor_sync(0xffffffffu, v, off);
    if ((threadIdx.x & 31) == 0) sbuf[threadIdx.x >> 5] = v;
    __syncthreads();
    if (threadIdx.x < 32) {
        float w = (threadIdx.x < 8) ? sbuf[threadIdx.x] : 0.f;
        #pragma unroll
        for (int off = 4; off > 0; off >>= 1) w += __shfl_xor_sync(0xffffffffu, w, off);
        if (threadIdx.x == 0) sbuf[0] = w;
    }
    __syncthreads();
    float r = sbuf[0];
    __syncthreads();
    return r;
}

__global__ __launch_bounds__(256) void combine_kernel(
    const float* __restrict__ go, const float* __restrict__ x,
    const float* __restrict__ ln_w, const float* __restrict__ lam,
    const float* __restrict__ final_ln_w, const float* __restrict__ alpha,
    float* __restrict__ y) {
    __shared__ float sbuf[8];
    const int row = blockIdx.x;      // b*T + t
    const int d0 = threadIdx.x * 4;

    // lambda weights (3 scalars, computed per-thread)
    float sg[NL]; float mean = 0.f;
    #pragma unroll
    for (int i = 0; i < NL; i++) { sg[i] = 1.f/(1.f + expf(-lam[i])); mean += sg[i]; }
    mean *= (1.f/NL);
    float var = 0.f;
    #pragma unroll
    for (int i = 0; i < NL; i++) var += (sg[i]-mean)*(sg[i]-mean);
    var *= (1.f/NL);
    float rv = rsqrtf(var + EPSF);
    float lw[NL];
    #pragma unroll
    for (int i = 0; i < NL; i++) lw[i] = (sg[i]-mean)*rv;

    float4 xv = *(const float4*)(x + (size_t)row*DD + d0);
    float a = alpha[0];
    float z[4] = { a*xv.x, a*xv.y, a*xv.z, a*xv.w };

    #pragma unroll
    for (int l = 0; l < NL; l++) {
        float4 ov = *(const float4*)(go + ((size_t)l*MROWS + row)*DD + d0);
        float ss = ov.x*ov.x + ov.y*ov.y + ov.z*ov.z + ov.w*ov.w;
        ss = blockReduceSum256(ss, sbuf);
        float c = lw[l] * rsqrtf(ss*(1.f/DD) + EPSF);
        z[0] += c * ln_w[l*DD + d0+0] * ov.x;
        z[1] += c * ln_w[l*DD + d0+1] * ov.y;
        z[2] += c * ln_w[l*DD + d0+2] * ov.z;
        z[3] += c * ln_w[l*DD + d0+3] * ov.w;
    }
    float zz = z[0]*z[0] + z[1]*z[1] + z[2]*z[2] + z[3]*z[3];
    zz = blockReduceSum256(zz, sbuf);
    float rz = rsqrtf(zz*(1.f/DD) + EPSF);
    float* yp = y + (size_t)row*DD + d0;
    yp[0] = z[0]*rz*final_ln_w[d0+0];
    yp[1] = z[1]*rz*final_ln_w[d0+1];
    yp[2] = z[2]*rz*final_ln_w[d0+2];
    yp[3] = z[3]*rz*final_ln_w[d0+3];
}

// ---------------- launch ----------------
extern "C" void kernel_launch(void* const* d_in, const int* in_sizes, int n_in,
                              void* d_out, int out_size) {
    const float* x          = (const float*)d_in[0];
    const float* cosb       = (const float*)d_in[1];
    const float* sinb       = (const float*)d_in[2];
    const float* q_w        = (const float*)d_in[3];
    const float* k_w        = (const float*)d_in[4];
    const float* v_w        = (const float*)d_in[5];
    const float* ln_w       = (const float*)d_in[6];
    const float* lam        = (const float*)d_in[7];
    const float* out_w      = (const float*)d_in[8];
    const float* final_ln_w = (const float*)d_in[9];
    const float* alpha      = (const float*)d_in[10];
    float* out = (float*)d_out;

    float *qtmp, *ktmp, *vtmp, *gq, *gK, *gV, *go, *gy;
    cudaGetSymbolAddress((void**)&qtmp, g_qtmp);
    cudaGetSymbolAddress((void**)&ktmp, g_ktmp);
    cudaGetSymbolAddress((void**)&vtmp, g_vtmp);
    cudaGetSymbolAddress((void**)&gq,   g_q);
    cudaGetSymbolAddress((void**)&gK,   g_Kc);
    cudaGetSymbolAddress((void**)&gV,   g_Vc);
    cudaGetSymbolAddress((void**)&go,   g_o);
    cudaGetSymbolAddress((void**)&gy,   g_y);

    const int ATTN_SMEM = 4*64*AP*4;  // 69632 B
    cudaFuncSetAttribute(attn_kernel, cudaFuncAttributeMaxDynamicSharedMemorySize, ATTN_SMEM);

    dim3 blk(256);
    // batched projections: x(2048x1024) against all layers' weights at once
    sgemm_nt<<<dim3(3072/128, 2048/128), blk>>>(x, q_w, qtmp, MROWS, NL*DD,   DD);
    sgemm_nt<<<dim3(1536/128, 2048/128), blk>>>(x, k_w, ktmp, MROWS, NL*DD/2, DD);
    sgemm_nt<<<dim3(1536/128, 2048/128), blk>>>(x, v_w, vtmp, MROWS, NL*DD/2, DD);

    rope_q_kernel<<<(NL*BB*TT*HH*32   + 255)/256, 256>>>(qtmp, cosb, sinb, gq);
    rope_k_kernel<<<(NL*BB*TT*NHKV*32 + 255)/256, 256>>>(ktmp, cosb, sinb, gK);
    copy_v_kernel<<<(NL*BB*TT*NHKV*64 + 255)/256, 256>>>(vtmp, gV);

    // all 3 layers' attention in one grid (independent once K/V scattered)
    attn_kernel<<<dim3(TT/64, BB*HH, NL), blk, ATTN_SMEM>>>(gq, gK, gV, go);

    combine_kernel<<<MROWS, blk>>>(go, x, ln_w, lam, final_ln_w, alpha, gy);

    sgemm_nt<<<dim3(1024/128, 2048/128), blk>>>(gy, out_w, out, MROWS, DD, DD);
}

// round 3
// speedup vs baseline: 2.2561x; 2.2561x over previous
#include <cuda_runtime.h>
#include <math.h>
#include <stdint.h>

// Problem constants
#define NL    3
#define BB    2
#define TT    1024
#define DD    1024
#define HH    16
#define NHKV  8
#define HDIM  64
#define MAXKV 3072
#define EPSF  1e-5f
#define MROWS (BB*TT)   // 2048

// ---------------- scratch (device globals; no cudaMalloc allowed) ----------------
__device__ float g_qtmp[MROWS * (NL*DD)];
__device__ float g_ktmp[MROWS * (NL*DD/2)];
__device__ float g_vtmp[MROWS * (NL*DD/2)];
__device__ float g_q [NL*BB*HH*TT*HDIM];         // rotated q (tf32-rounded)
__device__ float g_Kc[BB*NHKV*MAXKV*HDIM];       // rotated K (tf32-rounded)
__device__ float g_Vc[BB*NHKV*MAXKV*HDIM];       // V (tf32-rounded)
__device__ float g_o [NL*MROWS*DD];
__device__ float g_y [MROWS*DD];                 // pre-out-proj (tf32-rounded)
// tf32-rounded copies of GEMM inputs
__device__ float g_xr[MROWS*DD];
__device__ float g_wq[NL*DD*DD];
__device__ float g_wk[NL*(DD/2)*DD];
__device__ float g_wv[NL*(DD/2)*DD];
__device__ float g_wo[DD*DD];

// ---------------- helpers ----------------
__device__ __forceinline__ float cvt_tf32(float x) {
    uint32_t r;
    asm("cvt.rna.tf32.f32 %0, %1;" : "=r"(r) : "f"(x));
    return __uint_as_float(r);
}
__device__ __forceinline__ void mma8(float* d, const uint32_t* a, const uint32_t* b) {
    asm volatile(
        "mma.sync.aligned.m16n8k8.row.col.f32.tf32.tf32.f32 "
        "{%0,%1,%2,%3},{%4,%5,%6,%7},{%8,%9},{%0,%1,%2,%3};\n"
        : "+f"(d[0]), "+f"(d[1]), "+f"(d[2]), "+f"(d[3])
        : "r"(a[0]), "r"(a[1]), "r"(a[2]), "r"(a[3]), "r"(b[0]), "r"(b[1]));
}
__device__ __forceinline__ void cp_async16(float* s, const float* g) {
    uint32_t sa = (uint32_t)__cvta_generic_to_shared(s);
    asm volatile("cp.async.cg.shared.global [%0], [%1], 16;" :: "r"(sa), "l"(g));
}

// ---------------- round inputs to tf32 once ----------------
__global__ void round_tf32_kernel(const float* __restrict__ in, float* __restrict__ out, int n4) {
    int i = blockIdx.x * blockDim.x + threadIdx.x;
    if (i >= n4) return;
    float4 v = ((const float4*)in)[i];
    v.x = cvt_tf32(v.x); v.y = cvt_tf32(v.y); v.z = cvt_tf32(v.z); v.w = cvt_tf32(v.w);
    ((float4*)out)[i] = v;
}

// ---------------- TF32 tensor-core GEMM: C[M][N] = A[M][K] * B[N][K]^T ----------------
// 128x128 block tile, 256 thr (8 warps, 2x4 of 64x32 warp tiles), k-step 32,
// cp.async double-buffered. A,B already tf32-rounded. M,N%128==0, K%32==0.
#define GP 36          // smem pitch (floats) for a 32-wide k slice
#define GSTG ((128+128)*GP)   // floats per stage
__global__ __launch_bounds__(256) void gemm_tc(const float* __restrict__ A,
                                               const float* __restrict__ B,
                                               float* __restrict__ C,
                                               int M, int N, int K) {
    extern __shared__ float sm[];
    const int tid = threadIdx.x, w = tid >> 5, lane = tid & 31;
    const int lr = lane >> 2, lc = lane & 3;
    const int wm = w >> 2, wn = w & 3;
    const int bm = blockIdx.y * 128, bn = blockIdx.x * 128;

    float acc[4][4][4];
    #pragma unroll
    for (int i = 0; i < 4; i++)
        #pragma unroll
        for (int j = 0; j < 4; j++)
            #pragma unroll
            for (int r = 0; r < 4; r++) acc[i][j][r] = 0.f;

    const int NK = K >> 5;
    // prefetch stage 0
    {
        float* As = sm; float* Bs = sm + 128*GP;
        #pragma unroll
        for (int i = 0; i < 4; i++) {
            int idx = tid + i*256, r = idx >> 3, c = (idx & 7) * 4;
            cp_async16(&As[r*GP + c], A + (size_t)(bm + r)*K + c);
            cp_async16(&Bs[r*GP + c], B + (size_t)(bn + r)*K + c);
        }
        asm volatile("cp.async.commit_group;");
    }
    for (int kt = 0; kt < NK; kt++) {
        const int s = kt & 1;
        if (kt + 1 < NK) {
            float* As = sm + (s^1)*GSTG; float* Bs = As + 128*GP;
            int k0 = (kt+1) * 32;
            #pragma unroll
            for (int i = 0; i < 4; i++) {
                int idx = tid + i*256, r = idx >> 3, c = (idx & 7) * 4;
                cp_async16(&As[r*GP + c], A + (size_t)(bm + r)*K + k0 + c);
                cp_async16(&Bs[r*GP + c], B + (size_t)(bn + r)*K + k0 + c);
            }
        }
        asm volatile("cp.async.commit_group;");
        asm volatile("cp.async.wait_group 1;");
        __syncthreads();
        const float* As = sm + s*GSTG; const float* Bs = As + 128*GP;
        #pragma unroll
        for (int kc = 0; kc < 4; kc++) {
            uint32_t a[4][4], b[4][2];
            #pragma unroll
            for (int mf = 0; mf < 4; mf++) {
                int r = wm*64 + mf*16 + lr, c = kc*8 + lc;
                a[mf][0] = __float_as_uint(As[r*GP + c]);
                a[mf][1] = __float_as_uint(As[(r+8)*GP + c]);
                a[mf][2] = __float_as_uint(As[r*GP + c + 4]);
                a[mf][3] = __float_as_uint(As[(r+8)*GP + c + 4]);
            }
            #pragma unroll
            for (int nf = 0; nf < 4; nf++) {
                int rn = wn*32 + nf*8 + lr;
                b[nf][0] = __float_as_uint(Bs[rn*GP + kc*8 + lc]);
                b[nf][1] = __float_as_uint(Bs[rn*GP + kc*8 + lc + 4]);
            }
            #pragma unroll
            for (int mf = 0; mf < 4; mf++)
                #pragma unroll
                for (int nf = 0; nf < 4; nf++)
                    mma8(acc[mf][nf], a[mf], b[nf]);
        }
        __syncthreads();
    }
    #pragma unroll
    for (int mf = 0; mf < 4; mf++)
        #pragma unroll
        for (int nf = 0; nf < 4; nf++) {
            int r = bm + wm*64 + mf*16 + lr;
            int c = bn + wn*32 + nf*8 + 2*lc;
            *(float2*)&C[(size_t)r*N + c]     = make_float2(acc[mf][nf][0], acc[mf][nf][1]);
            *(float2*)&C[(size_t)(r+8)*N + c] = make_float2(acc[mf][nf][2], acc[mf][nf][3]);
        }
}

// ---------------- rope + scatter kernels (emit tf32-rounded values) ----------------
__global__ void rope_q_kernel(const float* __restrict__ qtmp,
                              const float* __restrict__ cosb,
                              const float* __restrict__ sinb,
                              float* __restrict__ gq) {
    int idx = blockIdx.x * blockDim.x + threadIdx.x;
    const int total = NL*BB*TT*HH*32;
    if (idx >= total) return;
    int d = idx & 31;  int r = idx >> 5;
    int h = r & 15;    r >>= 4;
    int t = r & 1023;  r >>= 10;
    int b = r & 1;     int l = r >> 1;
    const float* src = qtmp + (size_t)(b*TT + t)*(NL*DD) + l*DD + h*HDIM + d;
    float x1 = src[0], x2 = src[32];
    float c = cosb[t*32 + d], s = sinb[t*32 + d];
    float* dst = gq + ((size_t)((l*BB + b)*HH + h)*TT + t)*HDIM + d;
    dst[0]  = cvt_tf32(x1*c - x2*s);
    dst[32] = cvt_tf32(x2*c + x1*s);
}

__global__ void rope_k_kernel(const float* __restrict__ ktmp,
                              const float* __restrict__ cosb,
                              const float* __restrict__ sinb,
                              float* __restrict__ gK) {
    int idx = blockIdx.x * blockDim.x + threadIdx.x;
    const int total = NL*BB*TT*NHKV*32;
    if (idx >= total) return;
    int d = idx & 31;  int r = idx >> 5;
    int kvh = r & 7;   r >>= 3;
    int t = r & 1023;  r >>= 10;
    int b = r & 1;     int l = r >> 1;
    const float* src = ktmp + (size_t)(b*TT + t)*(NL*DD/2) + l*(DD/2) + kvh*HDIM + d;
    float x1 = src[0], x2 = src[32];
    int pos = l*TT + t;
    float c = cosb[pos*32 + d], s = sinb[pos*32 + d];
    float* dst = gK + ((size_t)(b*NHKV + kvh)*MAXKV + pos)*HDIM + d;
    dst[0]  = cvt_tf32(x1*c - x2*s);
    dst[32] = cvt_tf32(x2*c + x1*s);
}

__global__ void copy_v_kernel(const float* __restrict__ vtmp, float* __restrict__ gV) {
    int idx = blockIdx.x * blockDim.x + threadIdx.x;
    const int total = NL*BB*TT*NHKV*HDIM;
    if (idx >= total) return;
    int d = idx & 63;  int r = idx >> 6;
    int kvh = r & 7;   r >>= 3;
    int t = r & 1023;  r >>= 10;
    int b = r & 1;     int l = r >> 1;
    gV[((size_t)(b*NHKV + kvh)*MAXKV + l*TT + t)*HDIM + d] =
        cvt_tf32(vtmp[(size_t)(b*TT + t)*(NL*DD/2) + l*(DD/2) + kvh*HDIM + d]);
}

// ---------------- flash attention with TF32 tensor cores ----------------
// 128 threads (4 warps), 64-query tile, 64-key tiles, HDIM=64.
// Warp w owns query rows [w*16, w*16+16). Smem: Ps(Q-stage/P) pitch 68,
// Ks pitch 68, Vs pitch 72 (pitches chosen for conflict-free frag loads).
#define QP 68
#define VP 72
#define ATTN_SMEM_FLOATS (64*QP + 64*QP + 64*VP)
__global__ __launch_bounds__(128) void attn_tc(const float* __restrict__ gq,
                                               const float* __restrict__ gK,
                                               const float* __restrict__ gV,
                                               float* __restrict__ go) {
    extern __shared__ float sm[];
    float* Ps = sm;             // [64][QP] : Q staging, then P
    float* Ks = sm + 64*QP;     // [64][QP] : K tile, row=key, col=d
    float* Vs = sm + 2*64*QP;   // [64][VP] : V tile, row=key, col=d
    const int l  = (NL-1) - blockIdx.z;            // long layers first
    const int bh = blockIdx.y;
    const int b = bh >> 4, h = bh & 15, kvh = h >> 1;
    const int qt = (gridDim.x - 1) - blockIdx.x;   // long q-tiles first
    const int q0 = qt * 64;
    const int tid = threadIdx.x, w = tid >> 5, lane = tid & 31;
    const int lr = lane >> 2, lc = lane & 3;

    const float* Qb = gq + ((size_t)((l*BB + b)*HH + h)*TT + q0) * HDIM;
    const float* Kb = gK + (size_t)(b*NHKV + kvh) * MAXKV * HDIM;
    const float* Vb = gV + (size_t)(b*NHKV + kvh) * MAXKV * HDIM;

    // stage Q tile into Ps
    {
        int r = tid >> 1, c0 = (tid & 1) * 32;
        #pragma unroll
        for (int i = 0; i < 8; i++)
            *(float4*)&Ps[r*QP + c0 + i*4] = *(const float4*)(Qb + r*HDIM + c0 + i*4);
    }
    __syncthreads();
    // Q fragments (row-major A frags, m16 rows = warp's queries, k = d)
    uint32_t qa[8][4];
    #pragma unroll
    for (int kc = 0; kc < 8; kc++) {
        int r = w*16 + lr, c = kc*8 + lc;
        qa[kc][0] = __float_as_uint(Ps[r*QP + c]);
        qa[kc][1] = __float_as_uint(Ps[(r+8)*QP + c]);
        qa[kc][2] = __float_as_uint(Ps[r*QP + c + 4]);
        qa[kc][3] = __float_as_uint(Ps[(r+8)*QP + c + 4]);
    }

    float m0 = -1e30f, m1 = -1e30f, ls0 = 0.f, ls1 = 0.f;
    float O[8][4];
    #pragma unroll
    for (int i = 0; i < 8; i++)
        #pragma unroll
        for (int j = 0; j < 4; j++) O[i][j] = 0.f;

    const int nkt = l*16 + qt + 1;
    for (int kt = 0; kt < nkt; kt++) {
        __syncthreads();
        {   // load K,V tile (already tf32-rounded)
            int r = tid >> 1, c0 = (tid & 1) * 32;
            const float* Kp = Kb + (size_t)(kt*64 + r)*HDIM + c0;
            const float* Vp = Vb + (size_t)(kt*64 + r)*HDIM + c0;
            #pragma unroll
            for (int i = 0; i < 8; i++) {
                *(float4*)&Ks[r*QP + c0 + i*4] = *(const float4*)(Kp + i*4);
                *(float4*)&Vs[r*VP + c0 + i*4] = *(const float4*)(Vp + i*4);
            }
        }
        __syncthreads();

        // S = Q K^T : m16 (queries) x n64 (keys)
        float s[8][4];
        #pragma unroll
        for (int nc = 0; nc < 8; nc++) {
            s[nc][0] = s[nc][1] = s[nc][2] = s[nc][3] = 0.f;
            #pragma unroll
            for (int kc = 0; kc < 8; kc++) {
                uint32_t bfr[2];
                bfr[0] = __float_as_uint(Ks[(nc*8 + lr)*QP + kc*8 + lc]);
                bfr[1] = __float_as_uint(Ks[(nc*8 + lr)*QP + kc*8 + lc + 4]);
                mma8(s[nc], qa[kc], bfr);
            }
        }
        // scale + causal mask (diagonal tile only)
        const float scale = 0.125f;
        if (kt == nkt - 1) {
            int r0 = w*16 + lr, r1 = r0 + 8;
            #pragma unroll
            for (int nc = 0; nc < 8; nc++) {
                int c = nc*8 + 2*lc;
                s[nc][0] = (c   <= r0) ? s[nc][0]*scale : -1e30f;
                s[nc][1] = (c+1 <= r0) ? s[nc][1]*scale : -1e30f;
                s[nc][2] = (c   <= r1) ? s[nc][2]*scale : -1e30f;
                s[nc][3] = (c+1 <= r1) ? s[nc][3]*scale : -1e30f;
            }
        } else {
            #pragma unroll
            for (int nc = 0; nc < 8; nc++) {
                s[nc][0] *= scale; s[nc][1] *= scale;
                s[nc][2] *= scale; s[nc][3] *= scale;
            }
        }
        // online softmax on fragments; rows r0 (regs 0,1) and r1 (regs 2,3)
        float rmax0 = -1e30f, rmax1 = -1e30f;
        #pragma unroll
        for (int nc = 0; nc < 8; nc++) {
            rmax0 = fmaxf(rmax0, fmaxf(s[nc][0], s[nc][1]));
            rmax1 = fmaxf(rmax1, fmaxf(s[nc][2], s[nc][3]));
        }
        rmax0 = fmaxf(rmax0, __shfl_xor_sync(0xffffffffu, rmax0, 1));
        rmax0 = fmaxf(rmax0, __shfl_xor_sync(0xffffffffu, rmax0, 2));
        rmax1 = fmaxf(rmax1, __shfl_xor_sync(0xffffffffu, rmax1, 1));
        rmax1 = fmaxf(rmax1, __shfl_xor_sync(0xffffffffu, rmax1, 2));
        float mn0 = fmaxf(m0, rmax0), mn1 = fmaxf(m1, rmax1);
        float corr0 = __expf(m0 - mn0), corr1 = __expf(m1 - mn1);
        m0 = mn0; m1 = mn1;
        float ps0 = 0.f, ps1 = 0.f;
        #pragma unroll
        for (int nc = 0; nc < 8; nc++) {
            s[nc][0] = __expf(s[nc][0] - mn0); ps0 += s[nc][0];
            s[nc][1] = __expf(s[nc][1] - mn0); ps0 += s[nc][1];
            s[nc][2] = __expf(s[nc][2] - mn1); ps1 += s[nc][2];
            s[nc][3] = __expf(s[nc][3] - mn1); ps1 += s[nc][3];
        }
        ls0 = ls0*corr0 + ps0;  ls1 = ls1*corr1 + ps1;
        #pragma unroll
        for (int nf = 0; nf < 8; nf++) {
            O[nf][0] *= corr0; O[nf][1] *= corr0;
            O[nf][2] *= corr1; O[nf][3] *= corr1;
        }
        // store P (tf32-rounded) into warp-private rows of Ps
        {
            int r0 = w*16 + lr, r1 = r0 + 8;
            #pragma unroll
            for (int nc = 0; nc < 8; nc++) {
                int c = nc*8 + 2*lc;
                Ps[r0*QP + c]     = cvt_tf32(s[nc][0]);
                Ps[r0*QP + c + 1] = cvt_tf32(s[nc][1]);
                Ps[r1*QP + c]     = cvt_tf32(s[nc][2]);
                Ps[r1*QP + c + 1] = cvt_tf32(s[nc][3]);
            }
        }
        __syncwarp();
        // P fragments (A of PV), then O += P V
        uint32_t pa[8][4];
        #pragma unroll
        for (int kc = 0; kc < 8; kc++) {
            int r = w*16 + lr, c = kc*8 + lc;
            pa[kc][0] = __float_as_uint(Ps[r*QP + c]);
            pa[kc][1] = __float_as_uint(Ps[(r+8)*QP + c]);
            pa[kc][2] = __float_as_uint(Ps[r*QP + c + 4]);
            pa[kc][3] = __float_as_uint(Ps[(r+8)*QP + c + 4]);
        }
        #pragma unroll
        for (int nf = 0; nf < 8; nf++) {
            #pragma unroll
            for (int kc = 0; kc < 8; kc++) {
                uint32_t bfr[2];
                bfr[0] = __float_as_uint(Vs[(kc*8 + lc)*VP + nf*8 + lr]);
                bfr[1] = __float_as_uint(Vs[(kc*8 + lc + 4)*VP + nf*8 + lr]);
                mma8(O[nf], pa[kc], bfr);
            }
        }
    }
    // finalize: row sums across quad, divide, write out
    ls0 += __shfl_xor_sync(0xffffffffu, ls0, 1);
    ls0 += __shfl_xor_sync(0xffffffffu, ls0, 2);
    ls1 += __shfl_xor_sync(0xffffffffu, ls1, 1);
    ls1 += __shfl_xor_sync(0xffffffffu, ls1, 2);
    float inv0 = 1.f / ls0, inv1 = 1.f / ls1;
    int t0 = q0 + w*16 + lr, t1 = t0 + 8;
    #pragma unroll
    for (int nf = 0; nf < 8; nf++) {
        int c = h*HDIM + nf*8 + 2*lc;
        *(float2*)&go[((size_t)(l*BB + b)*TT + t0)*DD + c] =
            make_float2(O[nf][0]*inv0, O[nf][1]*inv0);
        *(float2*)&go[((size_t)(l*BB + b)*TT + t1)*DD + c] =
            make_float2(O[nf][2]*inv1, O[nf][3]*inv1);
    }
}

// ---------------- combine ----------------
__device__ __forceinline__ float blockReduceSum256(float v, float* sbuf) {
    #pragma unroll
    for (int off = 16; off > 0; off >>= 1) v += __shfl_xor_sync(0xffffffffu, v, off);
    if ((threadIdx.x & 31) == 0) sbuf[threadIdx.x >> 5] = v;
    __syncthreads();
    if (threadIdx.x < 32) {
        float w = (threadIdx.x < 8) ? sbuf[threadIdx.x] : 0.f;
        #pragma unroll
        for (int off = 4; off > 0; off >>= 1) w += __shfl_xor_sync(0xffffffffu, w, off);
        if (threadIdx.x == 0) sbuf[0] = w;
    }
    __syncthreads();
    float r = sbuf[0];
    __syncthreads();
    return r;
}

__global__ __launch_bounds__(256) void combine_kernel(
    const float* __restrict__ go, const float* __restrict__ x,
    const float* __restrict__ ln_w, const float* __restrict__ lam,
    const float* __restrict__ final_ln_w, const float* __restrict__ alpha,
    float* __restrict__ y) {
    __shared__ float sbuf[8];
    const int row = blockIdx.x;
    const int d0 = threadIdx.x * 4;

    float sg[NL]; float mean = 0.f;
    #pragma unroll
    for (int i = 0; i < NL; i++) { sg[i] = 1.f/(1.f + expf(-lam[i])); mean += sg[i]; }
    mean *= (1.f/NL);
    float var = 0.f;
    #pragma unroll
    for (int i = 0; i < NL; i++) var += (sg[i]-mean)*(sg[i]-mean);
    var *= (1.f/NL);
    float rv = rsqrtf(var + EPSF);
    float lw[NL];
    #pragma unroll
    for (int i = 0; i < NL; i++) lw[i] = (sg[i]-mean)*rv;

    float4 xv = *(const float4*)(x + (size_t)row*DD + d0);
    float a = alpha[0];
    float z[4] = { a*xv.x, a*xv.y, a*xv.z, a*xv.w };

    #pragma unroll
    for (int l = 0; l < NL; l++) {
        float4 ov = *(const float4*)(go + ((size_t)l*MROWS + row)*DD + d0);
        float ss = ov.x*ov.x + ov.y*ov.y + ov.z*ov.z + ov.w*ov.w;
        ss = blockReduceSum256(ss, sbuf);
        float c = lw[l] * rsqrtf(ss*(1.f/DD) + EPSF);
        z[0] += c * ln_w[l*DD + d0+0] * ov.x;
        z[1] += c * ln_w[l*DD + d0+1] * ov.y;
        z[2] += c * ln_w[l*DD + d0+2] * ov.z;
        z[3] += c * ln_w[l*DD + d0+3] * ov.w;
    }
    float zz = z[0]*z[0] + z[1]*z[1] + z[2]*z[2] + z[3]*z[3];
    zz = blockReduceSum256(zz, sbuf);
    float rz = rsqrtf(zz*(1.f/DD) + EPSF);
    float* yp = y + (size_t)row*DD + d0;
    yp[0] = cvt_tf32(z[0]*rz*final_ln_w[d0+0]);
    yp[1] = cvt_tf32(z[1]*rz*final_ln_w[d0+1]);
    yp[2] = cvt_tf32(z[2]*rz*final_ln_w[d0+2]);
    yp[3] = cvt_tf32(z[3]*rz*final_ln_w[d0+3]);
}

// ---------------- launch ----------------
extern "C" void kernel_launch(void* const* d_in, const int* in_sizes, int n_in,
                              void* d_out, int out_size) {
    const float* x          = (const float*)d_in[0];
    const float* cosb       = (const float*)d_in[1];
    const float* sinb       = (const float*)d_in[2];
    const float* q_w        = (const float*)d_in[3];
    const float* k_w        = (const float*)d_in[4];
    const float* v_w        = (const float*)d_in[5];
    const float* ln_w       = (const float*)d_in[6];
    const float* lam        = (const float*)d_in[7];
    const float* out_w      = (const float*)d_in[8];
    const float* final_ln_w = (const float*)d_in[9];
    const float* alpha      = (const float*)d_in[10];
    float* out = (float*)d_out;

    float *qtmp, *ktmp, *vtmp, *gq, *gK, *gV, *go, *gy;
    float *xr, *wq, *wk, *wv, *wo;
    cudaGetSymbolAddress((void**)&qtmp, g_qtmp);
    cudaGetSymbolAddress((void**)&ktmp, g_ktmp);
    cudaGetSymbolAddress((void**)&vtmp, g_vtmp);
    cudaGetSymbolAddress((void**)&gq,   g_q);
    cudaGetSymbolAddress((void**)&gK,   g_Kc);
    cudaGetSymbolAddress((void**)&gV,   g_Vc);
    cudaGetSymbolAddress((void**)&go,   g_o);
    cudaGetSymbolAddress((void**)&gy,   g_y);
    cudaGetSymbolAddress((void**)&xr,   g_xr);
    cudaGetSymbolAddress((void**)&wq,   g_wq);
    cudaGetSymbolAddress((void**)&wk,   g_wk);
    cudaGetSymbolAddress((void**)&wv,   g_wv);
    cudaGetSymbolAddress((void**)&wo,   g_wo);

    const int GEMM_SMEM = 2 * GSTG * 4;              // 73728 B
    const int ATTN_SMEM = ATTN_SMEM_FLOATS * 4;      // 53248 B
    cudaFuncSetAttribute(gemm_tc, cudaFuncAttributeMaxDynamicSharedMemorySize, GEMM_SMEM);
    cudaFuncSetAttribute(attn_tc, cudaFuncAttributeMaxDynamicSharedMemorySize, ATTN_SMEM);

    // round all GEMM inputs to tf32 once
    round_tf32_kernel<<<(MROWS*DD/4 + 255)/256, 256>>>(x, xr, MROWS*DD/4);
    round_tf32_kernel<<<(NL*DD*DD/4 + 255)/256, 256>>>(q_w, wq, NL*DD*DD/4);
    round_tf32_kernel<<<(NL*(DD/2)*DD/4 + 255)/256, 256>>>(k_w, wk, NL*(DD/2)*DD/4);
    round_tf32_kernel<<<(NL*(DD/2)*DD/4 + 255)/256, 256>>>(v_w, wv, NL*(DD/2)*DD/4);
    round_tf32_kernel<<<(DD*DD/4 + 255)/256, 256>>>(out_w, wo, DD*DD/4);

    // batched projections
    gemm_tc<<<dim3((NL*DD)/128,   MROWS/128), 256, GEMM_SMEM>>>(xr, wq, qtmp, MROWS, NL*DD,   DD);
    gemm_tc<<<dim3((NL*DD/2)/128, MROWS/128), 256, GEMM_SMEM>>>(xr, wk, ktmp, MROWS, NL*DD/2, DD);
    gemm_tc<<<dim3((NL*DD/2)/128, MROWS/128), 256, GEMM_SMEM>>>(xr, wv, vtmp, MROWS, NL*DD/2, DD);

    rope_q_kernel<<<(NL*BB*TT*HH*32   + 255)/256, 256>>>(qtmp, cosb, sinb, gq);
    rope_k_kernel<<<(NL*BB*TT*NHKV*32 + 255)/256, 256>>>(ktmp, cosb, sinb, gK);
    copy_v_kernel<<<(NL*BB*TT*NHKV*64 + 255)/256, 256>>>(vtmp, gV);

    attn_tc<<<dim3(TT/64, BB*HH, NL), 128, ATTN_SMEM>>>(gq, gK, gV, go);

    combine_kernel<<<MROWS, 256>>>(go, x, ln_w, lam, final_ln_w, alpha, gy);

    gemm_tc<<<dim3(DD/128, MROWS/128), 256, GEMM_SMEM>>>(gy, wo, out, MROWS, DD, DD);
}

// round 5
// speedup vs baseline: 3.7063x; 1.6428x over previous
#include <cuda_runtime.h>
#include <math.h>
#include <stdint.h>

// Problem constants
#define NL    3
#define BB    2
#define TT    1024
#define DD    1024
#define HH    16
#define NHKV  8
#define HDIM  64
#define MAXKV 3072
#define EPSF  1e-5f
#define MROWS (BB*TT)   // 2048

// ---------------- scratch (device globals; no cudaMalloc allowed) ----------------
__device__ float g_qkvtmp[MROWS * 6144];         // fused projections  50 MB
__device__ float g_wb[6144 * DD];                // concat rounded qkv weights 25 MB
__device__ float g_wo[DD*DD];                    // rounded out_w
__device__ float g_xr[MROWS*DD];                 // rounded x
__device__ float g_q [NL*BB*HH*TT*HDIM];         // rotated q (tf32-rounded)
__device__ float g_Kc[BB*NHKV*MAXKV*HDIM];       // rotated K (tf32-rounded)
__device__ float g_Vc[BB*NHKV*MAXKV*HDIM];       // V (tf32-rounded)
__device__ float g_o [NL*MROWS*DD];              // attention outputs
__device__ float g_y [MROWS*DD];                 // pre-out-proj (tf32-rounded)

// ---------------- helpers ----------------
__device__ __forceinline__ float cvt_tf32(float x) {
    uint32_t r;
    asm("cvt.rna.tf32.f32 %0, %1;" : "=r"(r) : "f"(x));
    return __uint_as_float(r);
}
__device__ __forceinline__ void mma8(float* d, const uint32_t* a, const uint32_t* b) {
    asm volatile(
        "mma.sync.aligned.m16n8k8.row.col.f32.tf32.tf32.f32 "
        "{%0,%1,%2,%3},{%4,%5,%6,%7},{%8,%9},{%0,%1,%2,%3};\n"
        : "+f"(d[0]), "+f"(d[1]), "+f"(d[2]), "+f"(d[3])
        : "r"(a[0]), "r"(a[1]), "r"(a[2]), "r"(a[3]), "r"(b[0]), "r"(b[1]));
}
__device__ __forceinline__ void cp_async16(float* s, const float* g) {
    uint32_t sa = (uint32_t)__cvta_generic_to_shared(s);
    asm volatile("cp.async.cg.shared.global [%0], [%1], 16;" :: "r"(sa), "l"(g));
}

// ---------------- merged tf32-rounding of all GEMM inputs (1 launch) ----------------
// segments (blocks of 256, float4 elements): x:2048 | q_w:3072 | k_w:1536 | v_w:1536 | out_w:1024
__global__ __launch_bounds__(256) void round_all_kernel(
    const float* __restrict__ x, const float* __restrict__ qw,
    const float* __restrict__ kw, const float* __restrict__ vw,
    const float* __restrict__ ow,
    float* __restrict__ xr, float* __restrict__ wb, float* __restrict__ wo) {
    int bid = blockIdx.x;
    const float* src; float* dst; int i;
    if (bid < 2048)      { src = x;  dst = xr;                 i = bid*256 + threadIdx.x; }
    else if (bid < 5120) { src = qw; dst = wb;                 i = (bid-2048)*256 + threadIdx.x; }
    else if (bid < 6656) { src = kw; dst = wb + 3072*DD;       i = (bid-5120)*256 + threadIdx.x; }
    else if (bid < 8192) { src = vw; dst = wb + 4608*DD;       i = (bid-6656)*256 + threadIdx.x; }
    else                 { src = ow; dst = wo;                 i = (bid-8192)*256 + threadIdx.x; }
    float4 v = ((const float4*)src)[i];
    v.x = cvt_tf32(v.x); v.y = cvt_tf32(v.y); v.z = cvt_tf32(v.z); v.w = cvt_tf32(v.w);
    ((float4*)dst)[i] = v;
}

// ---------------- TF32 tensor-core GEMM: C[M][N] = A[M][K] * B[N][K]^T ----------------
#define GP 36
#define GSTG ((128+128)*GP)
__global__ __launch_bounds__(256) void gemm_tc(const float* __restrict__ A,
                                               const float* __restrict__ B,
                                               float* __restrict__ C,
                                               int M, int N, int K) {
    extern __shared__ float sm[];
    const int tid = threadIdx.x, w = tid >> 5, lane = tid & 31;
    const int lr = lane >> 2, lc = lane & 3;
    const int wm = w >> 2, wn = w & 3;
    const int bm = blockIdx.y * 128, bn = blockIdx.x * 128;

    float acc[4][4][4];
    #pragma unroll
    for (int i = 0; i < 4; i++)
        #pragma unroll
        for (int j = 0; j < 4; j++)
            #pragma unroll
            for (int r = 0; r < 4; r++) acc[i][j][r] = 0.f;

    const int NK = K >> 5;
    {
        float* As = sm; float* Bs = sm + 128*GP;
        #pragma unroll
        for (int i = 0; i < 4; i++) {
            int idx = tid + i*256, r = idx >> 3, c = (idx & 7) * 4;
            cp_async16(&As[r*GP + c], A + (size_t)(bm + r)*K + c);
            cp_async16(&Bs[r*GP + c], B + (size_t)(bn + r)*K + c);
        }
        asm volatile("cp.async.commit_group;");
    }
    for (int kt = 0; kt < NK; kt++) {
        const int s = kt & 1;
        if (kt + 1 < NK) {
            float* As = sm + (s^1)*GSTG; float* Bs = As + 128*GP;
            int k0 = (kt+1) * 32;
            #pragma unroll
            for (int i = 0; i < 4; i++) {
                int idx = tid + i*256, r = idx >> 3, c = (idx & 7) * 4;
                cp_async16(&As[r*GP + c], A + (size_t)(bm + r)*K + k0 + c);
                cp_async16(&Bs[r*GP + c], B + (size_t)(bn + r)*K + k0 + c);
            }
        }
        asm volatile("cp.async.commit_group;");
        asm volatile("cp.async.wait_group 1;");
        __syncthreads();
        const float* As = sm + s*GSTG; const float* Bs = As + 128*GP;
        #pragma unroll
        for (int kc = 0; kc < 4; kc++) {
            uint32_t a[4][4], b[4][2];
            #pragma unroll
            for (int mf = 0; mf < 4; mf++) {
                int r = wm*64 + mf*16 + lr, c = kc*8 + lc;
                a[mf][0] = __float_as_uint(As[r*GP + c]);
                a[mf][1] = __float_as_uint(As[(r+8)*GP + c]);
                a[mf][2] = __float_as_uint(As[r*GP + c + 4]);
                a[mf][3] = __float_as_uint(As[(r+8)*GP + c + 4]);
            }
            #pragma unroll
            for (int nf = 0; nf < 4; nf++) {
                int rn = wn*32 + nf*8 + lr;
                b[nf][0] = __float_as_uint(Bs[rn*GP + kc*8 + lc]);
                b[nf][1] = __float_as_uint(Bs[rn*GP + kc*8 + lc + 4]);
            }
            #pragma unroll
            for (int mf = 0; mf < 4; mf++)
                #pragma unroll
                for (int nf = 0; nf < 4; nf++)
                    mma8(acc[mf][nf], a[mf], b[nf]);
        }
        __syncthreads();
    }
    #pragma unroll
    for (int mf = 0; mf < 4; mf++)
        #pragma unroll
        for (int nf = 0; nf < 4; nf++) {
            int r = bm + wm*64 + mf*16 + lr;
            int c = bn + wn*32 + nf*8 + 2*lc;
            *(float2*)&C[(size_t)r*N + c]     = make_float2(acc[mf][nf][0], acc[mf][nf][1]);
            *(float2*)&C[(size_t)(r+8)*N + c] = make_float2(acc[mf][nf][2], acc[mf][nf][3]);
        }
}

// ---------------- merged rope/scatter (1 launch) ----------------
// seg0: rope q (12288 blocks)  seg1: rope k (6144)  seg2: copy v vec4 (3072)
__global__ __launch_bounds__(256) void prep_kernel(const float* __restrict__ qkv,
                                                   const float* __restrict__ cosb,
                                                   const float* __restrict__ sinb,
                                                   float* __restrict__ gq,
                                                   float* __restrict__ gK,
                                                   float* __restrict__ gV) {
    int bid = blockIdx.x;
    if (bid < 12288) {
        int idx = bid*256 + threadIdx.x;          // NL*BB*TT*HH*32
        int d = idx & 31;  int r = idx >> 5;
        int h = r & 15;    r >>= 4;
        int t = r & 1023;  r >>= 10;
        int b = r & 1;     int l = r >> 1;
        const float* src = qkv + (size_t)(b*TT + t)*6144 + l*DD + h*HDIM + d;
        float x1 = src[0], x2 = src[32];
        float c = cosb[t*32 + d], s = sinb[t*32 + d];
        float* dst = gq + ((size_t)((l*BB + b)*HH + h)*TT + t)*HDIM + d;
        dst[0]  = cvt_tf32(x1*c - x2*s);
        dst[32] = cvt_tf32(x2*c + x1*s);
    } else if (bid < 18432) {
        int idx = (bid-12288)*256 + threadIdx.x;  // NL*BB*TT*NHKV*32
        int d = idx & 31;  int r = idx >> 5;
        int kvh = r & 7;   r >>= 3;
        int t = r & 1023;  r >>= 10;
        int b = r & 1;     int l = r >> 1;
        const float* src = qkv + (size_t)(b*TT + t)*6144 + 3072 + l*(DD/2) + kvh*HDIM + d;
        float x1 = src[0], x2 = src[32];
        int pos = l*TT + t;
        float c = cosb[pos*32 + d], s = sinb[pos*32 + d];
        float* dst = gK + ((size_t)(b*NHKV + kvh)*MAXKV + pos)*HDIM + d;
        dst[0]  = cvt_tf32(x1*c - x2*s);
        dst[32] = cvt_tf32(x2*c + x1*s);
    } else {
        int idx = (bid-18432)*256 + threadIdx.x;  // NL*BB*TT*NHKV*16 float4s
        int d4 = idx & 15; int r = idx >> 4;
        int kvh = r & 7;   r >>= 3;
        int t = r & 1023;  r >>= 10;
        int b = r & 1;     int l = r >> 1;
        float4 v = *(const float4*)(qkv + (size_t)(b*TT + t)*6144 + 4608 + l*(DD/2) + kvh*HDIM + d4*4);
        v.x = cvt_tf32(v.x); v.y = cvt_tf32(v.y); v.z = cvt_tf32(v.z); v.w = cvt_tf32(v.w);
        *(float4*)(gV + ((size_t)(b*NHKV + kvh)*MAXKV + l*TT + t)*HDIM + d4*4) = v;
    }
}

// ---------------- flash attention, TF32 TC, 128-query blocks, pipelined K/V ----------------
// 256 threads (8 warps, 16 queries each). 64-key tiles, cp.async double-buffered.
#define BQ 128
#define QP 68
#define VP 72
#define ATTN_SMEM_FLOATS (BQ*QP + 2*64*QP + 2*64*VP)   // 26624 floats = 106496 B
__global__ __launch_bounds__(256) void attn_tc(const float* __restrict__ gq,
                                               const float* __restrict__ gK,
                                               const float* __restrict__ gV,
                                               float* __restrict__ go) {
    extern __shared__ float sm[];
    float* Ps = sm;                       // [128][QP] : Q staging, then P (warp-private rows)
    float* Ks = sm + BQ*QP;               // 2 stages of [64][QP]
    float* Vs = sm + BQ*QP + 2*64*QP;     // 2 stages of [64][VP]
    const int l  = (NL-1) - blockIdx.z;               // long layers first
    const int bh = blockIdx.y;
    const int b = bh >> 4, h = bh & 15, kvh = h >> 1;
    const int qt = (gridDim.x - 1) - blockIdx.x;      // long q-tiles first
    const int q0 = qt * BQ;
    const int tid = threadIdx.x, w = tid >> 5, lane = tid & 31;
    const int lr = lane >> 2, lc = lane & 3;

    const float* Qb = gq + ((size_t)((l*BB + b)*HH + h)*TT + q0) * HDIM;
    const float* Kb = gK + (size_t)(b*NHKV + kvh) * MAXKV * HDIM;
    const float* Vb = gV + (size_t)(b*NHKV + kvh) * MAXKV * HDIM;

    // stage Q tile (128x64) into Ps
    #pragma unroll
    for (int i = 0; i < 8; i++) {
        int idx = tid + i*256, r = idx >> 4, c4 = (idx & 15) * 4;
        *(float4*)&Ps[r*QP + c4] = *(const float4*)(Qb + r*HDIM + c4);
    }
    const int nkt = l*16 + qt*2 + 2;
    // prefetch key tile 0 into stage 0
    #pragma unroll
    for (int i = 0; i < 4; i++) {
        int idx = tid + i*256, r = idx >> 4, c4 = (idx & 15) * 4;
        cp_async16(&Ks[r*QP + c4], Kb + (size_t)r*HDIM + c4);
        cp_async16(&Vs[r*VP + c4], Vb + (size_t)r*HDIM + c4);
    }
    asm volatile("cp.async.commit_group;");
    __syncthreads();

    // Q fragments
    uint32_t qa[8][4];
    #pragma unroll
    for (int kc = 0; kc < 8; kc++) {
        int r = w*16 + lr, c = kc*8 + lc;
        qa[kc][0] = __float_as_uint(Ps[r*QP + c]);
        qa[kc][1] = __float_as_uint(Ps[(r+8)*QP + c]);
        qa[kc][2] = __float_as_uint(Ps[r*QP + c + 4]);
        qa[kc][3] = __float_as_uint(Ps[(r+8)*QP + c + 4]);
    }

    float m0 = -1e30f, m1 = -1e30f, ls0 = 0.f, ls1 = 0.f;
    float O[8][4];
    #pragma unroll
    for (int i = 0; i < 8; i++)
        #pragma unroll
        for (int j = 0; j < 4; j++) O[i][j] = 0.f;

    for (int kt = 0; kt < nkt; kt++) {
        const int s = kt & 1;
        if (kt + 1 < nkt) {
            const float* Kp = Kb + (size_t)(kt+1)*64*HDIM;
            const float* Vp = Vb + (size_t)(kt+1)*64*HDIM;
            float* Kd = Ks + (s^1)*64*QP;
            float* Vd = Vs + (s^1)*64*VP;
            #pragma unroll
            for (int i = 0; i < 4; i++) {
                int idx = tid + i*256, r = idx >> 4, c4 = (idx & 15) * 4;
                cp_async16(&Kd[r*QP + c4], Kp + (size_t)r*HDIM + c4);
                cp_async16(&Vd[r*VP + c4], Vp + (size_t)r*HDIM + c4);
            }
        }
        asm volatile("cp.async.commit_group;");
        asm volatile("cp.async.wait_group 1;");
        __syncthreads();
        const float* Kc = Ks + s*64*QP;
        const float* Vc = Vs + s*64*VP;

        // S = Q K^T : m16 x n64
        float s4[8][4];
        #pragma unroll
        for (int nc = 0; nc < 8; nc++) {
            s4[nc][0] = s4[nc][1] = s4[nc][2] = s4[nc][3] = 0.f;
            #pragma unroll
            for (int kc = 0; kc < 8; kc++) {
                uint32_t bfr[2];
                bfr[0] = __float_as_uint(Kc[(nc*8 + lr)*QP + kc*8 + lc]);
                bfr[1] = __float_as_uint(Kc[(nc*8 + lr)*QP + kc*8 + lc + 4]);
                mma8(s4[nc], qa[kc], bfr);
            }
        }
        const float scale = 0.125f;
        const int off = q0 + (l<<10) - (kt<<6);   // >=64 for all but last two tiles
        if (off < 64) {
            int r0 = w*16 + lr + off, r1 = r0 + 8;
            #pragma unroll
            for (int nc = 0; nc < 8; nc++) {
                int c = nc*8 + 2*lc;
                s4[nc][0] = (c   <= r0) ? s4[nc][0]*scale : -1e30f;
                s4[nc][1] = (c+1 <= r0) ? s4[nc][1]*scale : -1e30f;
                s4[nc][2] = (c   <= r1) ? s4[nc][2]*scale : -1e30f;
                s4[nc][3] = (c+1 <= r1) ? s4[nc][3]*scale : -1e30f;
            }
        } else {
            #pragma unroll
            for (int nc = 0; nc < 8; nc++) {
                s4[nc][0] *= scale; s4[nc][1] *= scale;
                s4[nc][2] *= scale; s4[nc][3] *= scale;
            }
        }
        // online softmax
        float rmax0 = -1e30f, rmax1 = -1e30f;
        #pragma unroll
        for (int nc = 0; nc < 8; nc++) {
            rmax0 = fmaxf(rmax0, fmaxf(s4[nc][0], s4[nc][1]));
            rmax1 = fmaxf(rmax1, fmaxf(s4[nc][2], s4[nc][3]));
        }
        rmax0 = fmaxf(rmax0, __shfl_xor_sync(0xffffffffu, rmax0, 1));
        rmax0 = fmaxf(rmax0, __shfl_xor_sync(0xffffffffu, rmax0, 2));
        rmax1 = fmaxf(rmax1, __shfl_xor_sync(0xffffffffu, rmax1, 1));
        rmax1 = fmaxf(rmax1, __shfl_xor_sync(0xffffffffu, rmax1, 2));
        float mn0 = fmaxf(m0, rmax0), mn1 = fmaxf(m1, rmax1);
        float corr0 = __expf(m0 - mn0), corr1 = __expf(m1 - mn1);
        m0 = mn0; m1 = mn1;
        float ps0 = 0.f, ps1 = 0.f;
        #pragma unroll
        for (int nc = 0; nc < 8; nc++) {
            s4[nc][0] = __expf(s4[nc][0] - mn0); ps0 += s4[nc][0];
            s4[nc][1] = __expf(s4[nc][1] - mn0); ps0 += s4[nc][1];
            s4[nc][2] = __expf(s4[nc][2] - mn1); ps1 += s4[nc][2];
            s4[nc][3] = __expf(s4[nc][3] - mn1); ps1 += s4[nc][3];
        }
        ls0 = ls0*corr0 + ps0;  ls1 = ls1*corr1 + ps1;
        #pragma unroll
        for (int nf = 0; nf < 8; nf++) {
            O[nf][0] *= corr0; O[nf][1] *= corr0;
            O[nf][2] *= corr1; O[nf][3] *= corr1;
        }
        // store P (tf32) into warp-private rows of Ps
        {
            int r0 = w*16 + lr, r1 = r0 + 8;
            #pragma unroll
            for (int nc = 0; nc < 8; nc++) {
                int c = nc*8 + 2*lc;
                Ps[r0*QP + c]     = cvt_tf32(s4[nc][0]);
                Ps[r0*QP + c + 1] = cvt_tf32(s4[nc][1]);
                Ps[r1*QP + c]     = cvt_tf32(s4[nc][2]);
                Ps[r1*QP + c + 1] = cvt_tf32(s4[nc][3]);
            }
        }
        __syncwarp();
        uint32_t pa[8][4];
        #pragma unroll
        for (int kc = 0; kc < 8; kc++) {
            int r = w*16 + lr, c = kc*8 + lc;
            pa[kc][0] = __float_as_uint(Ps[r*QP + c]);
            pa[kc][1] = __float_as_uint(Ps[(r+8)*QP + c]);
            pa[kc][2] = __float_as_uint(Ps[r*QP + c + 4]);
            pa[kc][3] = __float_as_uint(Ps[(r+8)*QP + c + 4]);
        }
        #pragma unroll
        for (int nf = 0; nf < 8; nf++) {
            #pragma unroll
            for (int kc = 0; kc < 8; kc++) {
                uint32_t bfr[2];
                bfr[0] = __float_as_uint(Vc[(kc*8 + lc)*VP + nf*8 + lr]);
                bfr[1] = __float_as_uint(Vc[(kc*8 + lc + 4)*VP + nf*8 + lr]);
                mma8(O[nf], pa[kc], bfr);
            }
        }
        __syncthreads();   // all warps done reading stage s before it is overwritten
    }
    ls0 += __shfl_xor_sync(0xffffffffu, ls0, 1);
    ls0 += __shfl_xor_sync(0xffffffffu, ls0, 2);
    ls1 += __shfl_xor_sync(0xffffffffu, ls1, 1);
    ls1 += __shfl_xor_sync(0xffffffffu, ls1, 2);
    float inv0 = 1.f / ls0, inv1 = 1.f / ls1;
    int t0 = q0 + w*16 + lr, t1 = t0 + 8;
    #pragma unroll
    for (int nf = 0; nf < 8; nf++) {
        int c = h*HDIM + nf*8 + 2*lc;
        *(float2*)&go[((size_t)(l*BB + b)*TT + t0)*DD + c] =
            make_float2(O[nf][0]*inv0, O[nf][1]*inv0);
        *(float2*)&go[((size_t)(l*BB + b)*TT + t1)*DD + c] =
            make_float2(O[nf][2]*inv1, O[nf][3]*inv1);
    }
}

// ---------------- combine ----------------
__device__ __forceinline__ float blockReduceSum256(float v, float* sbuf) {
    #pragma unroll
    for (int off = 16; off > 0; off >>= 1) v += __shfl_xor_sync(0xffffffffu, v, off);
    if ((threadIdx.x & 31) == 0) sbuf[threadIdx.x >> 5] = v;
    __syncthreads();
    if (threadIdx.x < 32) {
        float w = (threadIdx.x < 8) ? sbuf[threadIdx.x] : 0.f;
        #pragma unroll
        for (int off = 4; off > 0; off >>= 1) w += __shfl_xor_sync(0xffffffffu, w, off);
        if (threadIdx.x == 0) sbuf[0] = w;
    }
    __syncthreads();
    float r = sbuf[0];
    __syncthreads();
    return r;
}

__global__ __launch_bounds__(256) void combine_kernel(
    const float* __restrict__ go, const float* __restrict__ x,
    const float* __restrict__ ln_w, const float* __restrict__ lam,
    const float* __restrict__ final_ln_w, const float* __restrict__ alpha,
    float* __restrict__ y) {
    __shared__ float sbuf[8];
    const int row = blockIdx.x;
    const int d0 = threadIdx.x * 4;

    float sg[NL]; float mean = 0.f;
    #pragma unroll
    for (int i = 0; i < NL; i++) { sg[i] = 1.f/(1.f + expf(-lam[i])); mean += sg[i]; }
    mean *= (1.f/NL);
    float var = 0.f;
    #pragma unroll
    for (int i = 0; i < NL; i++) var += (sg[i]-mean)*(sg[i]-mean);
    var *= (1.f/NL);
    float rv = rsqrtf(var + EPSF);
    float lw[NL];
    #pragma unroll
    for (int i = 0; i < NL; i++) lw[i] = (sg[i]-mean)*rv;

    float4 xv = *(const float4*)(x + (size_t)row*DD + d0);
    float a = alpha[0];
    float z[4] = { a*xv.x, a*xv.y, a*xv.z, a*xv.w };

    #pragma unroll
    for (int l = 0; l < NL; l++) {
        float4 ov = *(const float4*)(go + ((size_t)l*MROWS + row)*DD + d0);
        float ss = ov.x*ov.x + ov.y*ov.y + ov.z*ov.z + ov.w*ov.w;
        ss = blockReduceSum256(ss, sbuf);
        float c = lw[l] * rsqrtf(ss*(1.f/DD) + EPSF);
        z[0] += c * ln_w[l*DD + d0+0] * ov.x;
        z[1] += c * ln_w[l*DD + d0+1] * ov.y;
        z[2] += c * ln_w[l*DD + d0+2] * ov.z;
        z[3] += c * ln_w[l*DD + d0+3] * ov.w;
    }
    float zz = z[0]*z[0] + z[1]*z[1] + z[2]*z[2] + z[3]*z[3];
    zz = blockReduceSum256(zz, sbuf);
    float rz = rsqrtf(zz*(1.f/DD) + EPSF);
    float* yp = y + (size_t)row*DD + d0;
    yp[0] = cvt_tf32(z[0]*rz*final_ln_w[d0+0]);
    yp[1] = cvt_tf32(z[1]*rz*final_ln_w[d0+1]);
    yp[2] = cvt_tf32(z[2]*rz*final_ln_w[d0+2]);
    yp[3] = cvt_tf32(z[3]*rz*final_ln_w[d0+3]);
}

// ---------------- launch ----------------
extern "C" void kernel_launch(void* const* d_in, const int* in_sizes, int n_in,
                              void* d_out, int out_size) {
    const float* x          = (const float*)d_in[0];
    const float* cosb       = (const float*)d_in[1];
    const float* sinb       = (const float*)d_in[2];
    const float* q_w        = (const float*)d_in[3];
    const float* k_w        = (const float*)d_in[4];
    const float* v_w        = (const float*)d_in[5];
    const float* ln_w       = (const float*)d_in[6];
    const float* lam        = (const float*)d_in[7];
    const float* out_w      = (const float*)d_in[8];
    const float* final_ln_w = (const float*)d_in[9];
    const float* alpha      = (const float*)d_in[10];
    float* out = (float*)d_out;

    float *qkvtmp, *wb, *wo, *xr, *gq, *gK, *gV, *go, *gy;
    cudaGetSymbolAddress((void**)&qkvtmp, g_qkvtmp);
    cudaGetSymbolAddress((void**)&wb,     g_wb);
    cudaGetSymbolAddress((void**)&wo,     g_wo);
    cudaGetSymbolAddress((void**)&xr,     g_xr);
    cudaGetSymbolAddress((void**)&gq,     g_q);
    cudaGetSymbolAddress((void**)&gK,     g_Kc);
    cudaGetSymbolAddress((void**)&gV,     g_Vc);
    cudaGetSymbolAddress((void**)&go,     g_o);
    cudaGetSymbolAddress((void**)&gy,     g_y);

    const int GEMM_SMEM = 2 * GSTG * 4;              // 73728 B
    const int ATTN_SMEM = ATTN_SMEM_FLOATS * 4;      // 106496 B
    cudaFuncSetAttribute(gemm_tc, cudaFuncAttributeMaxDynamicSharedMemorySize, GEMM_SMEM);
    cudaFuncSetAttribute(attn_tc, cudaFuncAttributeMaxDynamicSharedMemorySize, ATTN_SMEM);

    // 1. round all GEMM inputs to tf32 (one launch)
    round_all_kernel<<<9216, 256>>>(x, q_w, k_w, v_w, out_w, xr, wb, wo);

    // 2. fused QKV projection: [2048,1024] x [6144,1024]^T -> [2048,6144]
    gemm_tc<<<dim3(6144/128, MROWS/128), 256, GEMM_SMEM>>>(xr, wb, qkvtmp, MROWS, 6144, DD);

    // 3. rope q/k + scatter v (one launch)
    prep_kernel<<<21504, 256>>>(qkvtmp, cosb, sinb, gq, gK, gV);

    // 4. attention, all layers
    attn_tc<<<dim3(TT/BQ, BB*HH, NL), 256, ATTN_SMEM>>>(gq, gK, gV, go);

    // 5. combine
    combine_kernel<<<MROWS, 256>>>(go, x, ln_w, lam, final_ln_w, alpha, gy);

    // 6. out-proj
    gemm_tc<<<dim3(DD/128, MROWS/128), 256, GEMM_SMEM>>>(gy, wo, out, MROWS, DD, DD);
}